// round 2
// baseline (speedup 1.0000x reference)
#include <cuda_runtime.h>
#include <cstdint>

#define Bc 4
#define Tc 2048
#define Cc 1024
#define NH 16
#define HD 64

// Scratch (alloc-free rule: __device__ globals).
// g_qkv layout: [3][B][NH][T][HD]
__device__ float g_qkv[(size_t)3 * Bc * NH * Tc * HD];
// g_y layout: [B][T][C]
__device__ float g_y[(size_t)Bc * Tc * Cc];

// ---------------------------------------------------------------------------
// Tiled SGEMM: C[64x64] per block, 256 threads, 4x4 micro-tile, BK=16.
// MODE 1: A = x param, epilogue scatters into g_qkv ([3][B][H][T][HD]) + bias
// MODE 2: A = g_y,    epilogue writes Cout[m*N+n] + bias[n]
// ---------------------------------------------------------------------------
template <int MODE>
__global__ void __launch_bounds__(256) gemm64(const float* __restrict__ A,
                                              const float* __restrict__ Bm,
                                              const float* __restrict__ bias,
                                              float* __restrict__ Cout,
                                              int N, int K) {
    __shared__ float As[16][64];  // [k][m]  (transposed for conflict-free reads)
    __shared__ float Bs[16][64];  // [k][n]

    const float* Ap = (MODE == 2) ? (const float*)g_y : A;

    const int tid = threadIdx.x;
    const int tx = tid & 15;
    const int ty = tid >> 4;
    const int row0 = blockIdx.y * 64;
    const int col0 = blockIdx.x * 64;

    const int t4 = tid * 4;
    const int am = t4 >> 4;   // 0..63
    const int ak = t4 & 15;   // 0,4,8,12
    const int bk = t4 >> 6;   // 0..15
    const int bn = t4 & 63;   // 0,4,..,60

    float acc[4][4];
#pragma unroll
    for (int i = 0; i < 4; i++)
#pragma unroll
        for (int j = 0; j < 4; j++) acc[i][j] = 0.0f;

    for (int k0 = 0; k0 < K; k0 += 16) {
        float4 va = *(const float4*)(Ap + (size_t)(row0 + am) * K + k0 + ak);
        As[ak + 0][am] = va.x;
        As[ak + 1][am] = va.y;
        As[ak + 2][am] = va.z;
        As[ak + 3][am] = va.w;
        *(float4*)&Bs[bk][bn] =
            *(const float4*)(Bm + (size_t)(k0 + bk) * N + col0 + bn);
        __syncthreads();
#pragma unroll
        for (int kk = 0; kk < 16; kk++) {
            float4 a = *(const float4*)&As[kk][ty * 4];
            float4 b = *(const float4*)&Bs[kk][tx * 4];
            float av[4] = {a.x, a.y, a.z, a.w};
            float bv[4] = {b.x, b.y, b.z, b.w};
#pragma unroll
            for (int i = 0; i < 4; i++)
#pragma unroll
                for (int j = 0; j < 4; j++) acc[i][j] += av[i] * bv[j];
        }
        __syncthreads();
    }

    float4 bv4 = *(const float4*)(bias + col0 + tx * 4);
    float bvv[4] = {bv4.x, bv4.y, bv4.z, bv4.w};

    if (MODE == 2) {
#pragma unroll
        for (int i = 0; i < 4; i++) {
            float4 r;
            r.x = acc[i][0] + bvv[0];
            r.y = acc[i][1] + bvv[1];
            r.z = acc[i][2] + bvv[2];
            r.w = acc[i][3] + bvv[3];
            *(float4*)(Cout + (size_t)(row0 + ty * 4 + i) * N + col0 + tx * 4) = r;
        }
    } else {
        // qkv scatter. col0 is a multiple of 64 -> 'which' and 'h' constant per block.
        const int which = col0 >> 10;        // n / 1024
        const int h = (col0 & 1023) >> 6;    // (n % 1024) / 64
        const int b = row0 >> 11;            // m / 2048
        const int t0 = row0 & 2047;          // m % 2048
        float* dst =
            g_qkv + ((((size_t)which * Bc + b) * NH + h) * Tc) * HD;
#pragma unroll
        for (int i = 0; i < 4; i++) {
            float4 r;
            r.x = acc[i][0] + bvv[0];
            r.y = acc[i][1] + bvv[1];
            r.z = acc[i][2] + bvv[2];
            r.w = acc[i][3] + bvv[3];
            *(float4*)(dst + (size_t)(t0 + ty * 4 + i) * HD + tx * 4) = r;
        }
    }
}

// ---------------------------------------------------------------------------
// fp32 flash attention with causal mask.
// block = (qtile, b*NH+h). 256 threads, 4x4 micro-tiles for both S and O.
// Dynamic smem: Qs[64][65] Ks[64][65] Vs[64][64] Ps[64][64] = 66048 bytes.
// ---------------------------------------------------------------------------
__global__ void __launch_bounds__(256) flash_attn_kernel() {
    extern __shared__ float sm[];
    float* Qs = sm;                // [64][65]
    float* Ks = Qs + 64 * 65;      // [64][65]
    float* Vs = Ks + 64 * 65;      // [64][64]
    float* Ps = Vs + 64 * 64;      // [64][64]

    const int tid = threadIdx.x;
    const int tx = tid & 15;
    const int ty = tid >> 4;
    const int bh = blockIdx.y;
    const int q0 = blockIdx.x * 64;

    const float* qb = g_qkv + (size_t)bh * Tc * HD;
    const float* kb = g_qkv + ((size_t)Bc * NH + bh) * Tc * HD;
    const float* vb = g_qkv + ((size_t)2 * Bc * NH + bh) * Tc * HD;

    // Load Q tile (padded rows, scalar stores)
    for (int i = tid * 4; i < 64 * 64; i += 1024) {
        int r = i >> 6, c = i & 63;
        float4 v = *(const float4*)(qb + (size_t)(q0 + r) * HD + c);
        Qs[r * 65 + c + 0] = v.x;
        Qs[r * 65 + c + 1] = v.y;
        Qs[r * 65 + c + 2] = v.z;
        Qs[r * 65 + c + 3] = v.w;
    }

    float m_i[4], l_i[4], o[4][4];
#pragma unroll
    for (int i = 0; i < 4; i++) {
        m_i[i] = -1e30f;
        l_i[i] = 0.0f;
#pragma unroll
        for (int j = 0; j < 4; j++) o[i][j] = 0.0f;
    }

    const int ntiles = blockIdx.x + 1;  // causal: only tiles with k0 <= q0
    for (int kt = 0; kt < ntiles; kt++) {
        const int k0 = kt * 64;
        __syncthreads();  // prev-iter PV reads done before overwriting K/V/P
        for (int i = tid * 4; i < 64 * 64; i += 1024) {
            int r = i >> 6, c = i & 63;
            float4 v = *(const float4*)(kb + (size_t)(k0 + r) * HD + c);
            Ks[r * 65 + c + 0] = v.x;
            Ks[r * 65 + c + 1] = v.y;
            Ks[r * 65 + c + 2] = v.z;
            Ks[r * 65 + c + 3] = v.w;
            *(float4*)&Vs[r * 64 + c] =
                *(const float4*)(vb + (size_t)(k0 + r) * HD + c);
        }
        __syncthreads();

        // S = Q K^T
        float s[4][4];
#pragma unroll
        for (int i = 0; i < 4; i++)
#pragma unroll
            for (int j = 0; j < 4; j++) s[i][j] = 0.0f;
#pragma unroll 8
        for (int kk = 0; kk < 64; kk++) {
            float av[4], bv[4];
#pragma unroll
            for (int i = 0; i < 4; i++) av[i] = Qs[(ty * 4 + i) * 65 + kk];
#pragma unroll
            for (int j = 0; j < 4; j++) bv[j] = Ks[(tx * 4 + j) * 65 + kk];
#pragma unroll
            for (int i = 0; i < 4; i++)
#pragma unroll
                for (int j = 0; j < 4; j++) s[i][j] += av[i] * bv[j];
        }

        const bool diag = (kt == blockIdx.x);
        float mx[4];
#pragma unroll
        for (int i = 0; i < 4; i++) {
#pragma unroll
            for (int j = 0; j < 4; j++) {
                s[i][j] *= 0.125f;  // 1/sqrt(64)
                if (diag && (tx * 4 + j) > (ty * 4 + i)) s[i][j] = -1e30f;
            }
            mx[i] = fmaxf(fmaxf(s[i][0], s[i][1]), fmaxf(s[i][2], s[i][3]));
        }
        // reduce max over the 16 tx-lanes (lane = (ty&1)*16 + tx)
#pragma unroll
        for (int off = 8; off > 0; off >>= 1)
#pragma unroll
            for (int i = 0; i < 4; i++)
                mx[i] = fmaxf(mx[i], __shfl_xor_sync(0xffffffffu, mx[i], off));

        float alpha[4], rs[4];
#pragma unroll
        for (int i = 0; i < 4; i++) {
            float mn = fmaxf(m_i[i], mx[i]);
            alpha[i] = __expf(m_i[i] - mn);
            m_i[i] = mn;
            float sum = 0.0f;
#pragma unroll
            for (int j = 0; j < 4; j++) {
                float p = __expf(s[i][j] - mn);
                s[i][j] = p;
                sum += p;
            }
            rs[i] = sum;
        }
#pragma unroll
        for (int off = 8; off > 0; off >>= 1)
#pragma unroll
            for (int i = 0; i < 4; i++)
                rs[i] += __shfl_xor_sync(0xffffffffu, rs[i], off);
#pragma unroll
        for (int i = 0; i < 4; i++) l_i[i] = l_i[i] * alpha[i] + rs[i];

        // stage P, rescale O
#pragma unroll
        for (int i = 0; i < 4; i++) {
            float4 p4 = make_float4(s[i][0], s[i][1], s[i][2], s[i][3]);
            *(float4*)&Ps[(ty * 4 + i) * 64 + tx * 4] = p4;
#pragma unroll
            for (int j = 0; j < 4; j++) o[i][j] *= alpha[i];
        }
        __syncthreads();

        // O += P V
#pragma unroll 8
        for (int kk = 0; kk < 64; kk++) {
            float4 b4 = *(const float4*)&Vs[kk * 64 + tx * 4];
            float bv[4] = {b4.x, b4.y, b4.z, b4.w};
#pragma unroll
            for (int i = 0; i < 4; i++) {
                float a = Ps[(ty * 4 + i) * 64 + kk];
#pragma unroll
                for (int j = 0; j < 4; j++) o[i][j] += a * bv[j];
            }
        }
    }

    // normalize + store into g_y [B][T][C]
    const int b = bh / NH;
    const int h = bh % NH;
#pragma unroll
    for (int i = 0; i < 4; i++) {
        float inv = 1.0f / l_i[i];
        int t = q0 + ty * 4 + i;
        float4 r = make_float4(o[i][0] * inv, o[i][1] * inv, o[i][2] * inv,
                               o[i][3] * inv);
        *(float4*)(g_y + ((size_t)b * Tc + t) * Cc + h * HD + tx * 4) = r;
    }
}

// ---------------------------------------------------------------------------
extern "C" void kernel_launch(void* const* d_in, const int* in_sizes, int n_in,
                              void* d_out, int out_size) {
    const float* x = (const float*)d_in[0];
    const float* w_attn = (const float*)d_in[1];
    const float* b_attn = (const float*)d_in[2];
    const float* w_proj = (const float*)d_in[3];
    const float* b_proj = (const float*)d_in[4];
    float* out = (float*)d_out;

    // 1) QKV = x @ w_attn + b_attn, scattered to [3][B][H][T][hd]
    gemm64<1><<<dim3(3 * Cc / 64, Bc * Tc / 64), 256>>>(x, w_attn, b_attn,
                                                        nullptr, 3 * Cc, Cc);

    // 2) causal flash attention -> g_y [B][T][C]
    const int smem_bytes = (64 * 65 * 2 + 64 * 64 * 2) * sizeof(float);  // 66048
    cudaFuncSetAttribute(flash_attn_kernel,
                         cudaFuncAttributeMaxDynamicSharedMemorySize, smem_bytes);
    flash_attn_kernel<<<dim3(Tc / 64, Bc * NH), 256, smem_bytes>>>();

    // 3) out = y @ w_proj + b_proj
    gemm64<2><<<dim3(Cc / 64, Bc * Tc / 64), 256>>>(nullptr, w_proj, b_proj,
                                                    out, Cc, Cc);
}

// round 4
// speedup vs baseline: 2.8821x; 2.8821x over previous
#include <cuda_runtime.h>
#include <cstdint>

#define Bc 4
#define Tc 2048
#define Cc 1024
#define NH 16
#define HD 64

// Scratch (alloc-free rule: __device__ globals).
__device__ float g_qkv[(size_t)3 * Bc * NH * Tc * HD];   // [3][B][H][T][HD]
__device__ float g_y[(size_t)Bc * Tc * Cc];              // [B][T][C]
__device__ float g_wT[(size_t)(3 * Cc + Cc) * Cc];       // w_attn^T then w_proj^T, [N][K], tf32-rounded

// ---------------------------------------------------------------------------
// Helpers
// ---------------------------------------------------------------------------
__device__ __forceinline__ uint32_t cvt_tf32u(float x) {
    uint32_t r;
    asm("cvt.rna.tf32.f32 %0, %1;" : "=r"(r) : "f"(x));
    return r;
}
__device__ __forceinline__ float cvt_tf32f(float x) {
    return __uint_as_float(cvt_tf32u(x));
}
// m16n8k8 tf32 mma: D += A*B. A row-major 16x8, B col-major 8x8, C/D fp32.
__device__ __forceinline__ void mma8(float* d, const uint32_t* a, const uint32_t* b) {
    asm volatile(
        "mma.sync.aligned.m16n8k8.row.col.f32.tf32.tf32.f32 "
        "{%0,%1,%2,%3}, {%4,%5,%6,%7}, {%8,%9}, {%0,%1,%2,%3};"
        : "+f"(d[0]), "+f"(d[1]), "+f"(d[2]), "+f"(d[3])
        : "r"(a[0]), "r"(a[1]), "r"(a[2]), "r"(a[3]), "r"(b[0]), "r"(b[1]));
}

// ---------------------------------------------------------------------------
// Weight transpose + tf32 rna rounding: W[K,N] row-major -> WT[N,K] (in g_wT+OFF)
// ---------------------------------------------------------------------------
template <size_t OFF, int NCOLS>
__global__ void __launch_bounds__(256) transpose_cvt(const float* __restrict__ W) {
    __shared__ float tile[32][33];
    const int n0 = blockIdx.x * 32, k0 = blockIdx.y * 32;
    const int tx = threadIdx.x, ty = threadIdx.y;  // 32 x 8
#pragma unroll
    for (int r = 0; r < 32; r += 8)
        tile[ty + r][tx] = W[(size_t)(k0 + ty + r) * NCOLS + n0 + tx];
    __syncthreads();
    float* WT = g_wT + OFF;
#pragma unroll
    for (int r = 0; r < 32; r += 8)
        WT[(size_t)(n0 + ty + r) * Cc + k0 + tx] = cvt_tf32f(tile[tx][ty + r]);
}

// ---------------------------------------------------------------------------
// tf32 mma.sync GEMM. Block 128 thr (4 warps), tile 128x128, warp tile 64x64,
// BK=32. A row-major [M,K]; B = WT [N,K] (pre-transposed, pre-rounded).
// Smem pad 36 floats/row: bank = (row*4 + k) mod 32 -> conflict-free frags.
// MODE 1: A = x, epilogue scatters into g_qkv (+bias)
// MODE 2: A = g_y, epilogue -> Cout (+bias)
// ---------------------------------------------------------------------------
template <int MODE>
__global__ void __launch_bounds__(128) mma_gemm(const float* __restrict__ A,
                                                const float* __restrict__ bias,
                                                float* __restrict__ Cout) {
    __shared__ float As[128 * 36];
    __shared__ float Bs[128 * 36];
    const uint32_t* Asu = (const uint32_t*)As;
    const uint32_t* Bsu = (const uint32_t*)Bs;

    const int tid = threadIdx.x;
    const int lane = tid & 31;
    const int wid = tid >> 5;
    const int g = lane >> 2;    // groupID (row within fragment)
    const int tig = lane & 3;   // thread-in-group (col within fragment)
    const int wm = wid >> 1;    // 0..1 -> 64-row band
    const int wn = wid & 1;     // 0..1 -> 64-col band
    const int row0 = blockIdx.y * 128;
    const int col0 = blockIdx.x * 128;

    const float* Asrc = (MODE == 2) ? (const float*)g_y : A;
    const float* Bsrc = (MODE == 2) ? g_wT + (size_t)3 * Cc * Cc : g_wT;

    float c[4][8][4];
#pragma unroll
    for (int mt = 0; mt < 4; mt++)
#pragma unroll
        for (int nt = 0; nt < 8; nt++)
#pragma unroll
            for (int j = 0; j < 4; j++) c[mt][nt][j] = 0.0f;

#pragma unroll 1
    for (int it = 0; it < 32; it++) {
        const int kb = it * 32;
        // stage A (cvt to tf32) and B (already tf32)
#pragma unroll
        for (int l = 0; l < 8; l++) {
            const int f = tid + l * 128;       // float4 index, 0..1023
            const int m = f >> 3;              // 0..127
            const int k4 = (f & 7) * 4;        // 0..28
            float4 va = *(const float4*)(Asrc + (size_t)(row0 + m) * Cc + kb + k4);
            va.x = cvt_tf32f(va.x); va.y = cvt_tf32f(va.y);
            va.z = cvt_tf32f(va.z); va.w = cvt_tf32f(va.w);
            *(float4*)&As[m * 36 + k4] = va;
            *(float4*)&Bs[m * 36 + k4] =
                *(const float4*)(Bsrc + (size_t)(col0 + m) * Cc + kb + k4);
        }
        __syncthreads();

#pragma unroll
        for (int ks = 0; ks < 4; ks++) {
            const int k0 = ks * 8;
            uint32_t a[4][4], b[8][2];
#pragma unroll
            for (int mt = 0; mt < 4; mt++) {
                const int base = (wm * 64 + mt * 16 + g) * 36 + k0 + tig;
                a[mt][0] = Asu[base];
                a[mt][1] = Asu[base + 8 * 36];
                a[mt][2] = Asu[base + 4];
                a[mt][3] = Asu[base + 8 * 36 + 4];
            }
#pragma unroll
            for (int nt = 0; nt < 8; nt++) {
                const int base = (wn * 64 + nt * 8 + g) * 36 + k0 + tig;
                b[nt][0] = Bsu[base];
                b[nt][1] = Bsu[base + 4];
            }
#pragma unroll
            for (int mt = 0; mt < 4; mt++)
#pragma unroll
                for (int nt = 0; nt < 8; nt++) mma8(c[mt][nt], a[mt], b[nt]);
        }
        __syncthreads();
    }

    // Epilogue
#pragma unroll
    for (int nt = 0; nt < 8; nt++) {
        const int n = col0 + wn * 64 + nt * 8 + tig * 2;
        const float b0 = bias[n], b1 = bias[n + 1];
        if (MODE == 2) {
#pragma unroll
            for (int mt = 0; mt < 4; mt++) {
                const int m = row0 + wm * 64 + mt * 16 + g;
                *(float2*)(Cout + (size_t)m * Cc + n) =
                    make_float2(c[mt][nt][0] + b0, c[mt][nt][1] + b1);
                *(float2*)(Cout + (size_t)(m + 8) * Cc + n) =
                    make_float2(c[mt][nt][2] + b0, c[mt][nt][3] + b1);
            }
        } else {
            const int which = n >> 10;
            const int rem = n & 1023;
            const int h = rem >> 6;
            const int d = rem & 63;
            const int bidx = row0 >> 11;
            const int t0 = row0 & 2047;
            float* base =
                g_qkv + ((((size_t)which * Bc + bidx) * NH + h) * Tc) * HD + d;
#pragma unroll
            for (int mt = 0; mt < 4; mt++) {
                const int r = t0 + wm * 64 + mt * 16 + g;
                *(float2*)(base + (size_t)r * HD) =
                    make_float2(c[mt][nt][0] + b0, c[mt][nt][1] + b1);
                *(float2*)(base + (size_t)(r + 8) * HD) =
                    make_float2(c[mt][nt][2] + b0, c[mt][nt][3] + b1);
            }
        }
    }
}

// ---------------------------------------------------------------------------
// Flash attention, tf32 mma.sync. Block 128 thr (4 warps), q-tile 64 rows,
// warp band = 16 q-rows. K-tiles of 64 keys, online softmax in fp32.
// Smem pad 68 floats/row (bank = row*4 + k mod 32): Q/K frag LDS conflict-free,
// V b-frags at worst 2-way.
// ---------------------------------------------------------------------------
__global__ void __launch_bounds__(128) flash_mma_kernel() {
    extern __shared__ float sm[];
    float* Qs = sm;                 // [64][68]
    float* Ks = Qs + 64 * 68;
    float* Vs = Ks + 64 * 68;
    float* Ps = Vs + 64 * 68;
    const uint32_t* Qsu = (const uint32_t*)Qs;
    const uint32_t* Ksu = (const uint32_t*)Ks;
    const uint32_t* Vsu = (const uint32_t*)Vs;
    const uint32_t* Psu = (const uint32_t*)Ps;

    const int tid = threadIdx.x;
    const int lane = tid & 31;
    const int w = tid >> 5;
    const int g = lane >> 2;
    const int tig = lane & 3;
    const int band = w * 16;
    const int bh = blockIdx.y;
    const int q0 = blockIdx.x * 64;

    const float* qb = g_qkv + (size_t)bh * Tc * HD;
    const float* kb = g_qkv + ((size_t)Bc * NH + bh) * Tc * HD;
    const float* vb = g_qkv + ((size_t)2 * Bc * NH + bh) * Tc * HD;

    // stage Q (cvt to tf32)
#pragma unroll
    for (int l = 0; l < 8; l++) {
        const int f = tid + l * 128;       // float4 idx 0..1023
        const int r = f >> 4, c4 = (f & 15) * 4;
        float4 v = *(const float4*)(qb + (size_t)(q0 + r) * HD + c4);
        v.x = cvt_tf32f(v.x); v.y = cvt_tf32f(v.y);
        v.z = cvt_tf32f(v.z); v.w = cvt_tf32f(v.w);
        *(float4*)&Qs[r * 68 + c4] = v;
    }
    __syncthreads();

    // preload Q fragments for this warp's 16-row band (fixed for whole kernel)
    uint32_t qf[8][4];
#pragma unroll
    for (int ks = 0; ks < 8; ks++) {
        const int base = (band + g) * 68 + ks * 8 + tig;
        qf[ks][0] = Qsu[base];
        qf[ks][1] = Qsu[base + 8 * 68];
        qf[ks][2] = Qsu[base + 4];
        qf[ks][3] = Qsu[base + 8 * 68 + 4];
    }

    float o[8][4];
#pragma unroll
    for (int nt = 0; nt < 8; nt++)
#pragma unroll
        for (int j = 0; j < 4; j++) o[nt][j] = 0.0f;
    float m_lo = -1e30f, m_hi = -1e30f, l_lo = 0.0f, l_hi = 0.0f;

    const int row_lo = q0 + band + g;
    const int row_hi = row_lo + 8;
    const int ntiles = blockIdx.x + 1;

#pragma unroll 1
    for (int kt = 0; kt < ntiles; kt++) {
        const int k0 = kt * 64;
        __syncthreads();  // prior iter's Vs/Ks reads complete
#pragma unroll
        for (int l = 0; l < 8; l++) {
            const int f = tid + l * 128;
            const int r = f >> 4, c4 = (f & 15) * 4;
            float4 vk = *(const float4*)(kb + (size_t)(k0 + r) * HD + c4);
            vk.x = cvt_tf32f(vk.x); vk.y = cvt_tf32f(vk.y);
            vk.z = cvt_tf32f(vk.z); vk.w = cvt_tf32f(vk.w);
            *(float4*)&Ks[r * 68 + c4] = vk;
            float4 vv = *(const float4*)(vb + (size_t)(k0 + r) * HD + c4);
            vv.x = cvt_tf32f(vv.x); vv.y = cvt_tf32f(vv.y);
            vv.z = cvt_tf32f(vv.z); vv.w = cvt_tf32f(vv.w);
            *(float4*)&Vs[r * 68 + c4] = vv;
        }
        __syncthreads();

        // S = Q K^T   (B col-major: b0 = K[key = nt*8+g][hd = ks*8+tig])
        float s[8][4];
#pragma unroll
        for (int nt = 0; nt < 8; nt++)
#pragma unroll
            for (int j = 0; j < 4; j++) s[nt][j] = 0.0f;
#pragma unroll
        for (int ks = 0; ks < 8; ks++) {
            uint32_t b[8][2];
#pragma unroll
            for (int nt = 0; nt < 8; nt++) {
                const int base = (nt * 8 + g) * 68 + ks * 8 + tig;
                b[nt][0] = Ksu[base];
                b[nt][1] = Ksu[base + 4];
            }
#pragma unroll
            for (int nt = 0; nt < 8; nt++) mma8(s[nt], qf[ks], b[nt]);
        }

        // scale + causal mask
        const bool diag = (kt == blockIdx.x);
#pragma unroll
        for (int nt = 0; nt < 8; nt++) {
            const int cb = k0 + nt * 8 + tig * 2;
            s[nt][0] *= 0.125f; s[nt][1] *= 0.125f;
            s[nt][2] *= 0.125f; s[nt][3] *= 0.125f;
            if (diag) {
                if (cb > row_lo) s[nt][0] = -1e30f;
                if (cb + 1 > row_lo) s[nt][1] = -1e30f;
                if (cb > row_hi) s[nt][2] = -1e30f;
                if (cb + 1 > row_hi) s[nt][3] = -1e30f;
            }
        }

        // row max over 64 cols (quad shuffle: lanes xor 1, xor 2)
        float mx_lo = -1e30f, mx_hi = -1e30f;
#pragma unroll
        for (int nt = 0; nt < 8; nt++) {
            mx_lo = fmaxf(mx_lo, fmaxf(s[nt][0], s[nt][1]));
            mx_hi = fmaxf(mx_hi, fmaxf(s[nt][2], s[nt][3]));
        }
        mx_lo = fmaxf(mx_lo, __shfl_xor_sync(0xffffffffu, mx_lo, 1));
        mx_lo = fmaxf(mx_lo, __shfl_xor_sync(0xffffffffu, mx_lo, 2));
        mx_hi = fmaxf(mx_hi, __shfl_xor_sync(0xffffffffu, mx_hi, 1));
        mx_hi = fmaxf(mx_hi, __shfl_xor_sync(0xffffffffu, mx_hi, 2));

        const float mn_lo = fmaxf(m_lo, mx_lo);
        const float mn_hi = fmaxf(m_hi, mx_hi);
        const float alpha_lo = __expf(m_lo - mn_lo);
        const float alpha_hi = __expf(m_hi - mn_hi);
        m_lo = mn_lo; m_hi = mn_hi;

        float sum_lo = 0.0f, sum_hi = 0.0f;
#pragma unroll
        for (int nt = 0; nt < 8; nt++) {
            s[nt][0] = __expf(s[nt][0] - mn_lo);
            s[nt][1] = __expf(s[nt][1] - mn_lo);
            s[nt][2] = __expf(s[nt][2] - mn_hi);
            s[nt][3] = __expf(s[nt][3] - mn_hi);
            sum_lo += s[nt][0] + s[nt][1];
            sum_hi += s[nt][2] + s[nt][3];
        }
        sum_lo += __shfl_xor_sync(0xffffffffu, sum_lo, 1);
        sum_lo += __shfl_xor_sync(0xffffffffu, sum_lo, 2);
        sum_hi += __shfl_xor_sync(0xffffffffu, sum_hi, 1);
        sum_hi += __shfl_xor_sync(0xffffffffu, sum_hi, 2);
        l_lo = l_lo * alpha_lo + sum_lo;
        l_hi = l_hi * alpha_hi + sum_hi;

        // rescale O; stage P (tf32) into Ps (each warp touches only its band)
#pragma unroll
        for (int nt = 0; nt < 8; nt++) {
            o[nt][0] *= alpha_lo; o[nt][1] *= alpha_lo;
            o[nt][2] *= alpha_hi; o[nt][3] *= alpha_hi;
            const int cc = nt * 8 + tig * 2;
            *(float2*)&Ps[(band + g) * 68 + cc] =
                make_float2(cvt_tf32f(s[nt][0]), cvt_tf32f(s[nt][1]));
            *(float2*)&Ps[(band + g + 8) * 68 + cc] =
                make_float2(cvt_tf32f(s[nt][2]), cvt_tf32f(s[nt][3]));
        }
        __syncwarp();

        // O += P V   (b0 = V[key = ks*8+tig][hd = nt*8+g])
#pragma unroll
        for (int ks = 0; ks < 8; ks++) {
            uint32_t a[4];
            const int base = (band + g) * 68 + ks * 8 + tig;
            a[0] = Psu[base];
            a[1] = Psu[base + 8 * 68];
            a[2] = Psu[base + 4];
            a[3] = Psu[base + 8 * 68 + 4];
            uint32_t b[8][2];
#pragma unroll
            for (int nt = 0; nt < 8; nt++) {
                b[nt][0] = Vsu[(ks * 8 + tig) * 68 + nt * 8 + g];
                b[nt][1] = Vsu[(ks * 8 + tig + 4) * 68 + nt * 8 + g];
            }
#pragma unroll
            for (int nt = 0; nt < 8; nt++) mma8(o[nt], a, b[nt]);
        }
    }

    // normalize + store into g_y [B][T][C]
    const float inv_lo = 1.0f / l_lo;
    const float inv_hi = 1.0f / l_hi;
    const int b = bh / NH;
    const int h = bh % NH;
    const int t_lo = q0 + band + g;
#pragma unroll
    for (int nt = 0; nt < 8; nt++) {
        const int col = h * HD + nt * 8 + tig * 2;
        *(float2*)(g_y + ((size_t)b * Tc + t_lo) * Cc + col) =
            make_float2(o[nt][0] * inv_lo, o[nt][1] * inv_lo);
        *(float2*)(g_y + ((size_t)b * Tc + t_lo + 8) * Cc + col) =
            make_float2(o[nt][2] * inv_hi, o[nt][3] * inv_hi);
    }
}

// ---------------------------------------------------------------------------
extern "C" void kernel_launch(void* const* d_in, const int* in_sizes, int n_in,
                              void* d_out, int out_size) {
    const float* x = (const float*)d_in[0];
    const float* w_attn = (const float*)d_in[1];
    const float* b_attn = (const float*)d_in[2];
    const float* w_proj = (const float*)d_in[3];
    const float* b_proj = (const float*)d_in[4];
    float* out = (float*)d_out;

    // 0) pre-transpose weights (+tf32 rna rounding)
    transpose_cvt<0, 3 * Cc><<<dim3(3 * Cc / 32, Cc / 32), dim3(32, 8)>>>(w_attn);
    transpose_cvt<(size_t)3 * Cc * Cc, Cc><<<dim3(Cc / 32, Cc / 32), dim3(32, 8)>>>(w_proj);

    // 1) QKV = x @ w_attn + b_attn (tf32 mma.sync), scatter -> g_qkv
    mma_gemm<1><<<dim3(3 * Cc / 128, Bc * Tc / 128), 128>>>(x, b_attn, nullptr);

    // 2) causal flash attention (tf32 mma.sync) -> g_y
    const int fa_smem = 4 * 64 * 68 * sizeof(float);  // 69632
    cudaFuncSetAttribute(flash_mma_kernel,
                         cudaFuncAttributeMaxDynamicSharedMemorySize, fa_smem);
    flash_mma_kernel<<<dim3(Tc / 64, Bc * NH), 128, fa_smem>>>();

    // 3) out = y @ w_proj + b_proj (tf32 mma.sync)
    mma_gemm<2><<<dim3(Cc / 128, Bc * Tc / 128), 128>>>(nullptr, b_proj, out);
}

// round 5
// speedup vs baseline: 3.3694x; 1.1691x over previous
#include <cuda_runtime.h>
#include <cstdint>

#define Bc 4
#define Tc 2048
#define Cc 1024
#define NH 16
#define HD 64

// Scratch (alloc-free rule: __device__ globals).
__device__ float g_x[(size_t)Bc * Tc * Cc];               // tf32-rounded x
__device__ float g_qkv[(size_t)3 * Bc * NH * Tc * HD];    // [3][B][H][T][HD], tf32-rounded
__device__ float g_y[(size_t)Bc * Tc * Cc];               // [B][T][C], tf32-rounded
__device__ float g_wT[(size_t)(3 * Cc + Cc) * Cc];        // w_attn^T then w_proj^T, [N][K], tf32-rounded

// ---------------------------------------------------------------------------
// Helpers
// ---------------------------------------------------------------------------
__device__ __forceinline__ uint32_t smem_u32(const void* p) {
    uint32_t a;
    asm("{ .reg .u64 t; cvta.to.shared.u64 t, %1; cvt.u32.u64 %0, t; }"
        : "=r"(a) : "l"(p));
    return a;
}
__device__ __forceinline__ float cvt_tf32f(float x) {
    uint32_t r;
    asm("cvt.rna.tf32.f32 %0, %1;" : "=r"(r) : "f"(x));
    return __uint_as_float(r);
}
// m16n8k8 tf32 mma: D += A*B. A row-major 16x8, B col-major 8x8, C/D fp32.
__device__ __forceinline__ void mma8(float* d, const uint32_t* a, const uint32_t* b) {
    asm volatile(
        "mma.sync.aligned.m16n8k8.row.col.f32.tf32.tf32.f32 "
        "{%0,%1,%2,%3}, {%4,%5,%6,%7}, {%8,%9}, {%0,%1,%2,%3};"
        : "+f"(d[0]), "+f"(d[1]), "+f"(d[2]), "+f"(d[3])
        : "r"(a[0]), "r"(a[1]), "r"(a[2]), "r"(a[3]), "r"(b[0]), "r"(b[1]));
}
__device__ __forceinline__ void cp_async16(uint32_t dst, const void* src) {
    asm volatile("cp.async.cg.shared.global [%0], [%1], 16;" :: "r"(dst), "l"(src));
}
__device__ __forceinline__ void cp_commit() {
    asm volatile("cp.async.commit_group;");
}
template <int N>
__device__ __forceinline__ void cp_wait() {
    asm volatile("cp.async.wait_group %0;" :: "n"(N));
}

// ---------------------------------------------------------------------------
// x -> g_x with tf32 rna rounding
// ---------------------------------------------------------------------------
__global__ void __launch_bounds__(256) cvt_x_kernel(const float* __restrict__ x) {
    const size_t i = ((size_t)blockIdx.x * 256 + threadIdx.x) * 4;
    float4 v = *(const float4*)(x + i);
    v.x = cvt_tf32f(v.x); v.y = cvt_tf32f(v.y);
    v.z = cvt_tf32f(v.z); v.w = cvt_tf32f(v.w);
    *(float4*)(g_x + i) = v;
}

// ---------------------------------------------------------------------------
// Weight transpose + tf32 rna rounding: W[K,N] row-major -> WT[N,K] (g_wT+OFF)
// ---------------------------------------------------------------------------
template <size_t OFF, int NCOLS>
__global__ void __launch_bounds__(256) transpose_cvt(const float* __restrict__ W) {
    __shared__ float tile[32][33];
    const int n0 = blockIdx.x * 32, k0 = blockIdx.y * 32;
    const int tx = threadIdx.x, ty = threadIdx.y;  // 32 x 8
#pragma unroll
    for (int r = 0; r < 32; r += 8)
        tile[ty + r][tx] = W[(size_t)(k0 + ty + r) * NCOLS + n0 + tx];
    __syncthreads();
    float* WT = g_wT + OFF;
#pragma unroll
    for (int r = 0; r < 32; r += 8)
        WT[(size_t)(n0 + ty + r) * Cc + k0 + tx] = cvt_tf32f(tile[tx][ty + r]);
}

// ---------------------------------------------------------------------------
// tf32 mma.sync GEMM with cp.async double buffering.
// 256 thr (8 warps), tile 128x128, warp tile 64x32, BK=32.
// A (pre-rounded) row-major [M,K]; B = WT [N,K] (pre-rounded).
// Smem pad 36 floats/row (144B, 16B-aligned for cp.async).
// MODE 1: A = g_x, epilogue scatters tf32-rounded into g_qkv (+bias)
// MODE 2: A = g_y, epilogue -> Cout fp32 (+bias)
// ---------------------------------------------------------------------------
template <int MODE>
__global__ void __launch_bounds__(256, 2) mma_gemm(const float* __restrict__ bias,
                                                   float* __restrict__ Cout) {
    extern __shared__ float smg[];
    float* As = smg;                 // [2][128*36]
    float* Bs = smg + 2 * 128 * 36;  // [2][128*36]

    const int tid = threadIdx.x;
    const int lane = tid & 31;
    const int wid = tid >> 5;
    const int g = lane >> 2;
    const int tig = lane & 3;
    const int wm = wid >> 2;   // 0..1 -> 64-row band
    const int wn = wid & 3;    // 0..3 -> 32-col band
    const int row0 = blockIdx.y * 128;
    const int col0 = blockIdx.x * 128;

    const float* Asrc = (MODE == 2) ? (const float*)g_y : g_x;
    const float* Bsrc = (MODE == 2) ? g_wT + (size_t)3 * Cc * Cc : g_wT;

    // staging geometry: thread covers rows m0+32l (l=0..3), cols k4..k4+3
    const int m0 = tid >> 3;
    const int k4 = (tid & 7) * 4;
    const uint32_t sA0 = smem_u32(As);
    const uint32_t sB0 = smem_u32(Bs);

    float c[4][4][4];
#pragma unroll
    for (int mt = 0; mt < 4; mt++)
#pragma unroll
        for (int nt = 0; nt < 4; nt++)
#pragma unroll
            for (int j = 0; j < 4; j++) c[mt][nt][j] = 0.0f;

    // prologue: stage 0
#pragma unroll
    for (int l = 0; l < 4; l++) {
        const int m = m0 + 32 * l;
        cp_async16(sA0 + (m * 36 + k4) * 4, Asrc + (size_t)(row0 + m) * Cc + k4);
        cp_async16(sB0 + (m * 36 + k4) * 4, Bsrc + (size_t)(col0 + m) * Cc + k4);
    }
    cp_commit();

#pragma unroll 1
    for (int it = 0; it < 32; it++) {
        if (it + 1 < 32) {
            const int kb = (it + 1) * 32;
            const uint32_t off = ((it + 1) & 1) * 128 * 36 * 4;
#pragma unroll
            for (int l = 0; l < 4; l++) {
                const int m = m0 + 32 * l;
                cp_async16(sA0 + off + (m * 36 + k4) * 4,
                           Asrc + (size_t)(row0 + m) * Cc + kb + k4);
                cp_async16(sB0 + off + (m * 36 + k4) * 4,
                           Bsrc + (size_t)(col0 + m) * Cc + kb + k4);
            }
            cp_commit();
            cp_wait<1>();
        } else {
            cp_wait<0>();
        }
        __syncthreads();

        const uint32_t* Asu = (const uint32_t*)(As + (it & 1) * 128 * 36);
        const uint32_t* Bsu = (const uint32_t*)(Bs + (it & 1) * 128 * 36);
#pragma unroll
        for (int ks = 0; ks < 4; ks++) {
            const int k0 = ks * 8;
            uint32_t a[4][4], b[4][2];
#pragma unroll
            for (int mt = 0; mt < 4; mt++) {
                const int base = (wm * 64 + mt * 16 + g) * 36 + k0 + tig;
                a[mt][0] = Asu[base];
                a[mt][1] = Asu[base + 8 * 36];
                a[mt][2] = Asu[base + 4];
                a[mt][3] = Asu[base + 8 * 36 + 4];
            }
#pragma unroll
            for (int nt = 0; nt < 4; nt++) {
                const int base = (wn * 32 + nt * 8 + g) * 36 + k0 + tig;
                b[nt][0] = Bsu[base];
                b[nt][1] = Bsu[base + 4];
            }
#pragma unroll
            for (int mt = 0; mt < 4; mt++)
#pragma unroll
                for (int nt = 0; nt < 4; nt++) mma8(c[mt][nt], a[mt], b[nt]);
        }
        __syncthreads();
    }

    // Epilogue
#pragma unroll
    for (int nt = 0; nt < 4; nt++) {
        const int n = col0 + wn * 32 + nt * 8 + tig * 2;
        const float b0 = bias[n], b1 = bias[n + 1];
        if (MODE == 2) {
#pragma unroll
            for (int mt = 0; mt < 4; mt++) {
                const int m = row0 + wm * 64 + mt * 16 + g;
                *(float2*)(Cout + (size_t)m * Cc + n) =
                    make_float2(c[mt][nt][0] + b0, c[mt][nt][1] + b1);
                *(float2*)(Cout + (size_t)(m + 8) * Cc + n) =
                    make_float2(c[mt][nt][2] + b0, c[mt][nt][3] + b1);
            }
        } else {
            const int which = n >> 10;
            const int rem = n & 1023;
            const int h = rem >> 6;
            const int d = rem & 63;
            const int bidx = row0 >> 11;
            const int t0 = row0 & 2047;
            float* base =
                g_qkv + ((((size_t)which * Bc + bidx) * NH + h) * Tc) * HD + d;
#pragma unroll
            for (int mt = 0; mt < 4; mt++) {
                const int r = t0 + wm * 64 + mt * 16 + g;
                *(float2*)(base + (size_t)r * HD) =
                    make_float2(cvt_tf32f(c[mt][nt][0] + b0), cvt_tf32f(c[mt][nt][1] + b1));
                *(float2*)(base + (size_t)(r + 8) * HD) =
                    make_float2(cvt_tf32f(c[mt][nt][2] + b0), cvt_tf32f(c[mt][nt][3] + b1));
            }
        }
    }
}

// ---------------------------------------------------------------------------
// Flash attention, tf32 mma.sync. 256 thr (8 warps), q-tile 128 rows,
// warp band = 16 q-rows, kv-tiles of 64 keys, online softmax fp32.
// Inputs pre-rounded tf32 -> staging has no cvt. Per-warp causal tile skip.
// ---------------------------------------------------------------------------
__global__ void __launch_bounds__(256, 2) flash_mma_kernel() {
    extern __shared__ float sm[];
    float* Qs = sm;                  // [128][68]
    float* Ks = Qs + 128 * 68;       // [64][68]
    float* Vs = Ks + 64 * 68;        // [64][68]
    float* Ps = Vs + 64 * 68;        // [128][68]
    const uint32_t* Qsu = (const uint32_t*)Qs;
    const uint32_t* Ksu = (const uint32_t*)Ks;
    const uint32_t* Vsu = (const uint32_t*)Vs;
    const uint32_t* Psu = (const uint32_t*)Ps;

    const int tid = threadIdx.x;
    const int lane = tid & 31;
    const int w = tid >> 5;
    const int g = lane >> 2;
    const int tig = lane & 3;
    const int band = w * 16;
    const int bh = blockIdx.y;
    const int q0 = blockIdx.x * 128;

    const float* qb = g_qkv + (size_t)bh * Tc * HD;
    const float* kb = g_qkv + ((size_t)Bc * NH + bh) * Tc * HD;
    const float* vb = g_qkv + ((size_t)2 * Bc * NH + bh) * Tc * HD;

    // stage Q (no cvt: pre-rounded)
#pragma unroll
    for (int l = 0; l < 8; l++) {
        const int r = (tid >> 4) + 16 * l;
        const int c4 = (tid & 15) * 4;
        *(float4*)&Qs[r * 68 + c4] = *(const float4*)(qb + (size_t)(q0 + r) * HD + c4);
    }
    __syncthreads();

    // preload Q fragments for this warp's 16-row band
    uint32_t qf[8][4];
#pragma unroll
    for (int ks = 0; ks < 8; ks++) {
        const int base = (band + g) * 68 + ks * 8 + tig;
        qf[ks][0] = Qsu[base];
        qf[ks][1] = Qsu[base + 8 * 68];
        qf[ks][2] = Qsu[base + 4];
        qf[ks][3] = Qsu[base + 8 * 68 + 4];
    }

    float o[8][4];
#pragma unroll
    for (int nt = 0; nt < 8; nt++)
#pragma unroll
        for (int j = 0; j < 4; j++) o[nt][j] = 0.0f;
    float m_lo = -1e30f, m_hi = -1e30f, l_lo = 0.0f, l_hi = 0.0f;

    const int row_lo = q0 + band + g;
    const int row_hi = row_lo + 8;
    const int ntiles = 2 * blockIdx.x + 2;

#pragma unroll 1
    for (int kt = 0; kt < ntiles; kt++) {
        const int k0 = kt * 64;
        __syncthreads();  // all warps done reading prior Ks/Vs
#pragma unroll
        for (int l = 0; l < 4; l++) {
            const int r = (tid >> 4) + 16 * l;
            const int c4 = (tid & 15) * 4;
            *(float4*)&Ks[r * 68 + c4] = *(const float4*)(kb + (size_t)(k0 + r) * HD + c4);
            *(float4*)&Vs[r * 68 + c4] = *(const float4*)(vb + (size_t)(k0 + r) * HD + c4);
        }
        __syncthreads();

        if (k0 > q0 + band + 15) continue;  // tile fully masked for this warp

        // S = Q K^T
        float s[8][4];
#pragma unroll
        for (int nt = 0; nt < 8; nt++)
#pragma unroll
            for (int j = 0; j < 4; j++) s[nt][j] = 0.0f;
#pragma unroll
        for (int ks = 0; ks < 8; ks++) {
            uint32_t b[8][2];
#pragma unroll
            for (int nt = 0; nt < 8; nt++) {
                const int base = (nt * 8 + g) * 68 + ks * 8 + tig;
                b[nt][0] = Ksu[base];
                b[nt][1] = Ksu[base + 4];
            }
#pragma unroll
            for (int nt = 0; nt < 8; nt++) mma8(s[nt], qf[ks], b[nt]);
        }

        // scale + causal mask (only near the diagonal)
        const bool diag = (k0 + 63 > q0 + band);
#pragma unroll
        for (int nt = 0; nt < 8; nt++) {
            const int cb = k0 + nt * 8 + tig * 2;
            s[nt][0] *= 0.125f; s[nt][1] *= 0.125f;
            s[nt][2] *= 0.125f; s[nt][3] *= 0.125f;
            if (diag) {
                if (cb > row_lo) s[nt][0] = -1e30f;
                if (cb + 1 > row_lo) s[nt][1] = -1e30f;
                if (cb > row_hi) s[nt][2] = -1e30f;
                if (cb + 1 > row_hi) s[nt][3] = -1e30f;
            }
        }

        // row max over 64 cols (quad shuffle)
        float mx_lo = -1e30f, mx_hi = -1e30f;
#pragma unroll
        for (int nt = 0; nt < 8; nt++) {
            mx_lo = fmaxf(mx_lo, fmaxf(s[nt][0], s[nt][1]));
            mx_hi = fmaxf(mx_hi, fmaxf(s[nt][2], s[nt][3]));
        }
        mx_lo = fmaxf(mx_lo, __shfl_xor_sync(0xffffffffu, mx_lo, 1));
        mx_lo = fmaxf(mx_lo, __shfl_xor_sync(0xffffffffu, mx_lo, 2));
        mx_hi = fmaxf(mx_hi, __shfl_xor_sync(0xffffffffu, mx_hi, 1));
        mx_hi = fmaxf(mx_hi, __shfl_xor_sync(0xffffffffu, mx_hi, 2));

        const float mn_lo = fmaxf(m_lo, mx_lo);
        const float mn_hi = fmaxf(m_hi, mx_hi);
        const float alpha_lo = __expf(m_lo - mn_lo);
        const float alpha_hi = __expf(m_hi - mn_hi);
        m_lo = mn_lo; m_hi = mn_hi;

        float sum_lo = 0.0f, sum_hi = 0.0f;
#pragma unroll
        for (int nt = 0; nt < 8; nt++) {
            s[nt][0] = __expf(s[nt][0] - mn_lo);
            s[nt][1] = __expf(s[nt][1] - mn_lo);
            s[nt][2] = __expf(s[nt][2] - mn_hi);
            s[nt][3] = __expf(s[nt][3] - mn_hi);
            sum_lo += s[nt][0] + s[nt][1];
            sum_hi += s[nt][2] + s[nt][3];
        }
        sum_lo += __shfl_xor_sync(0xffffffffu, sum_lo, 1);
        sum_lo += __shfl_xor_sync(0xffffffffu, sum_lo, 2);
        sum_hi += __shfl_xor_sync(0xffffffffu, sum_hi, 1);
        sum_hi += __shfl_xor_sync(0xffffffffu, sum_hi, 2);
        l_lo = l_lo * alpha_lo + sum_lo;
        l_hi = l_hi * alpha_hi + sum_hi;

        // rescale O; stage P (tf32) into this warp's band of Ps
#pragma unroll
        for (int nt = 0; nt < 8; nt++) {
            o[nt][0] *= alpha_lo; o[nt][1] *= alpha_lo;
            o[nt][2] *= alpha_hi; o[nt][3] *= alpha_hi;
            const int cc = nt * 8 + tig * 2;
            *(float2*)&Ps[(band + g) * 68 + cc] =
                make_float2(cvt_tf32f(s[nt][0]), cvt_tf32f(s[nt][1]));
            *(float2*)&Ps[(band + g + 8) * 68 + cc] =
                make_float2(cvt_tf32f(s[nt][2]), cvt_tf32f(s[nt][3]));
        }
        __syncwarp();

        // O += P V
#pragma unroll
        for (int ks = 0; ks < 8; ks++) {
            uint32_t a[4];
            const int base = (band + g) * 68 + ks * 8 + tig;
            a[0] = Psu[base];
            a[1] = Psu[base + 8 * 68];
            a[2] = Psu[base + 4];
            a[3] = Psu[base + 8 * 68 + 4];
            uint32_t b[8][2];
#pragma unroll
            for (int nt = 0; nt < 8; nt++) {
                b[nt][0] = Vsu[(ks * 8 + tig) * 68 + nt * 8 + g];
                b[nt][1] = Vsu[(ks * 8 + tig + 4) * 68 + nt * 8 + g];
            }
#pragma unroll
            for (int nt = 0; nt < 8; nt++) mma8(o[nt], a, b[nt]);
        }
    }

    // normalize + store tf32-rounded into g_y [B][T][C]
    const float inv_lo = 1.0f / l_lo;
    const float inv_hi = 1.0f / l_hi;
    const int b = bh / NH;
    const int h = bh % NH;
    const int t_lo = q0 + band + g;
#pragma unroll
    for (int nt = 0; nt < 8; nt++) {
        const int col = h * HD + nt * 8 + tig * 2;
        *(float2*)(g_y + ((size_t)b * Tc + t_lo) * Cc + col) =
            make_float2(cvt_tf32f(o[nt][0] * inv_lo), cvt_tf32f(o[nt][1] * inv_lo));
        *(float2*)(g_y + ((size_t)b * Tc + t_lo + 8) * Cc + col) =
            make_float2(cvt_tf32f(o[nt][2] * inv_hi), cvt_tf32f(o[nt][3] * inv_hi));
    }
}

// ---------------------------------------------------------------------------
extern "C" void kernel_launch(void* const* d_in, const int* in_sizes, int n_in,
                              void* d_out, int out_size) {
    const float* x = (const float*)d_in[0];
    const float* w_attn = (const float*)d_in[1];
    const float* b_attn = (const float*)d_in[2];
    const float* w_proj = (const float*)d_in[3];
    const float* b_proj = (const float*)d_in[4];
    float* out = (float*)d_out;

    // 0) pre-round x; pre-transpose + round weights
    cvt_x_kernel<<<(Bc * Tc * Cc) / (256 * 4), 256>>>(x);
    transpose_cvt<0, 3 * Cc><<<dim3(3 * Cc / 32, Cc / 32), dim3(32, 8)>>>(w_attn);
    transpose_cvt<(size_t)3 * Cc * Cc, Cc><<<dim3(Cc / 32, Cc / 32), dim3(32, 8)>>>(w_proj);

    const int gemm_smem = 4 * 128 * 36 * sizeof(float);  // 73728
    cudaFuncSetAttribute(mma_gemm<1>, cudaFuncAttributeMaxDynamicSharedMemorySize, gemm_smem);
    cudaFuncSetAttribute(mma_gemm<2>, cudaFuncAttributeMaxDynamicSharedMemorySize, gemm_smem);

    // 1) QKV = x @ w_attn + b_attn (tf32 mma + cp.async), scatter -> g_qkv
    mma_gemm<1><<<dim3(3 * Cc / 128, Bc * Tc / 128), 256, gemm_smem>>>(b_attn, nullptr);

    // 2) causal flash attention (tf32 mma) -> g_y
    const int fa_smem = (128 * 68 + 64 * 68 * 2 + 128 * 68) * sizeof(float);  // 104448
    cudaFuncSetAttribute(flash_mma_kernel,
                         cudaFuncAttributeMaxDynamicSharedMemorySize, fa_smem);
    flash_mma_kernel<<<dim3(Tc / 128, Bc * NH), 256, fa_smem>>>();

    // 3) out = y @ w_proj + b_proj (tf32 mma + cp.async)
    mma_gemm<2><<<dim3(Cc / 128, Bc * Tc / 128), 256, gemm_smem>>>(b_proj, out);
}

// round 6
// speedup vs baseline: 7.2286x; 2.1453x over previous
#include <cuda_runtime.h>
#include <cuda_fp16.h>
#include <cstdint>

#define Bc 4
#define Tc 2048
#define Cc 1024
#define NH 16
#define HD 64

// Scratch (alloc-free rule: __device__ globals). All fp16.
__device__ __half g_x[(size_t)Bc * Tc * Cc];               // fp16 x
__device__ __half g_qkv[(size_t)3 * Bc * NH * Tc * HD];    // [3][B][H][T][HD]
__device__ __half g_y[(size_t)Bc * Tc * Cc];               // [B][T][C]
__device__ __half g_wT[(size_t)(3 * Cc + Cc) * Cc];        // w_attn^T then w_proj^T, [N][K]

// ---------------------------------------------------------------------------
// Helpers
// ---------------------------------------------------------------------------
__device__ __forceinline__ uint32_t smem_u32(const void* p) {
    uint32_t a;
    asm("{ .reg .u64 t; cvta.to.shared.u64 t, %1; cvt.u32.u64 %0, t; }"
        : "=r"(a) : "l"(p));
    return a;
}
// m16n8k16 fp16 mma, fp32 accum.
__device__ __forceinline__ void mma16(float* d, const uint32_t* a, uint32_t b0, uint32_t b1) {
    asm volatile(
        "mma.sync.aligned.m16n8k16.row.col.f32.f16.f16.f32 "
        "{%0,%1,%2,%3}, {%4,%5,%6,%7}, {%8,%9}, {%0,%1,%2,%3};"
        : "+f"(d[0]), "+f"(d[1]), "+f"(d[2]), "+f"(d[3])
        : "r"(a[0]), "r"(a[1]), "r"(a[2]), "r"(a[3]), "r"(b0), "r"(b1));
}
#define LDSM4(r0, r1, r2, r3, addr)                                        \
    asm volatile("ldmatrix.sync.aligned.m8n8.x4.shared.b16 {%0,%1,%2,%3}, [%4];" \
                 : "=r"(r0), "=r"(r1), "=r"(r2), "=r"(r3) : "r"(addr))
#define LDSM4T(r0, r1, r2, r3, addr)                                       \
    asm volatile("ldmatrix.sync.aligned.m8n8.x4.trans.shared.b16 {%0,%1,%2,%3}, [%4];" \
                 : "=r"(r0), "=r"(r1), "=r"(r2), "=r"(r3) : "r"(addr))
__device__ __forceinline__ void cp_async16(uint32_t dst, const void* src) {
    asm volatile("cp.async.cg.shared.global [%0], [%1], 16;" :: "r"(dst), "l"(src));
}
__device__ __forceinline__ void cp_commit() { asm volatile("cp.async.commit_group;"); }
template <int N>
__device__ __forceinline__ void cp_wait() {
    asm volatile("cp.async.wait_group %0;" :: "n"(N));
}

// ---------------------------------------------------------------------------
// x -> g_x fp16 (8 floats / thread)
// ---------------------------------------------------------------------------
__global__ void __launch_bounds__(256) cvt_x_kernel(const float* __restrict__ x) {
    const size_t i = ((size_t)blockIdx.x * 256 + threadIdx.x) * 8;
    float4 v0 = *(const float4*)(x + i);
    float4 v1 = *(const float4*)(x + i + 4);
    __half2 h[4];
    h[0] = __floats2half2_rn(v0.x, v0.y);
    h[1] = __floats2half2_rn(v0.z, v0.w);
    h[2] = __floats2half2_rn(v1.x, v1.y);
    h[3] = __floats2half2_rn(v1.z, v1.w);
    *(float4*)(g_x + i) = *(float4*)h;
}

// ---------------------------------------------------------------------------
// Weight transpose + fp16: W[K,N] fp32 row-major -> WT[N,K] fp16 (g_wT+OFF)
// ---------------------------------------------------------------------------
template <size_t OFF, int NCOLS>
__global__ void __launch_bounds__(256) transpose_cvt(const float* __restrict__ W) {
    __shared__ float tile[32][33];
    const int n0 = blockIdx.x * 32, k0 = blockIdx.y * 32;
    const int tx = threadIdx.x, ty = threadIdx.y;  // 32 x 8
#pragma unroll
    for (int r = 0; r < 32; r += 8)
        tile[ty + r][tx] = W[(size_t)(k0 + ty + r) * NCOLS + n0 + tx];
    __syncthreads();
    __half* WT = g_wT + OFF;
#pragma unroll
    for (int r = 0; r < 32; r += 8)
        WT[(size_t)(n0 + ty + r) * Cc + k0 + tx] = __float2half_rn(tile[tx][ty + r]);
}

// ---------------------------------------------------------------------------
// fp16 mma GEMM with cp.async double buffering.
// 256 thr (8 warps), tile 128x128, warp tile 64x32, BK=64 halves.
// Smem rows padded to 72 halves (144B): 8-row ldmatrix phases conflict-free.
// MODE 1: A = g_x, epilogue scatters fp16 into g_qkv (+bias)
// MODE 2: A = g_y, epilogue -> Cout fp32 (+bias)
// ---------------------------------------------------------------------------
#define GST 72  // smem row stride in halves
template <int MODE>
__global__ void __launch_bounds__(256, 2) mma_gemm(const float* __restrict__ bias,
                                                   float* __restrict__ Cout) {
    extern __shared__ __half smh[];
    __half* As = smh;                  // [2][128*GST]
    __half* Bs = smh + 2 * 128 * GST;  // [2][128*GST]

    const int tid = threadIdx.x;
    const int lane = tid & 31;
    const int wid = tid >> 5;
    const int g = lane >> 2;
    const int tig = lane & 3;
    const int wm = wid >> 2;   // 0..1 -> 64-row band
    const int wn = wid & 3;    // 0..3 -> 32-col band
    const int row0 = blockIdx.y * 128;
    const int col0 = blockIdx.x * 128;

    const __half* Asrc = (MODE == 2) ? g_y : g_x;
    const __half* Bsrc = (MODE == 2) ? g_wT + (size_t)3 * Cc * Cc : g_wT;

    const uint32_t sA0 = smem_u32(As);
    const uint32_t sB0 = smem_u32(Bs);
    // staging: chunk c = tid + l*256 -> row = c>>3, col8 = (c&7)*8 halves
    const int srow = tid >> 3;
    const int scol = (tid & 7) * 8;

    float c[4][4][4];
#pragma unroll
    for (int mt = 0; mt < 4; mt++)
#pragma unroll
        for (int nt = 0; nt < 4; nt++)
#pragma unroll
            for (int j = 0; j < 4; j++) c[mt][nt][j] = 0.0f;

    // prologue: stage 0
#pragma unroll
    for (int l = 0; l < 4; l++) {
        const int m = srow + 32 * l;
        cp_async16(sA0 + (m * GST + scol) * 2, Asrc + (size_t)(row0 + m) * Cc + scol);
        cp_async16(sB0 + (m * GST + scol) * 2, Bsrc + (size_t)(col0 + m) * Cc + scol);
    }
    cp_commit();

    // per-warp ldmatrix lane geometry
    const int arow = (lane & 15);
    const int acol = (lane >> 4) * 8;
    const int brow = (lane & 7) + ((lane >> 4) & 1) * 8;
    const int bcol = ((lane >> 3) & 1) * 8;

#pragma unroll 1
    for (int it = 0; it < 16; it++) {  // K = 1024 / 64
        if (it + 1 < 16) {
            const int kb = (it + 1) * 64;
            const uint32_t off = ((it + 1) & 1) * 128 * GST * 2;
#pragma unroll
            for (int l = 0; l < 4; l++) {
                const int m = srow + 32 * l;
                cp_async16(sA0 + off + (m * GST + scol) * 2,
                           Asrc + (size_t)(row0 + m) * Cc + kb + scol);
                cp_async16(sB0 + off + (m * GST + scol) * 2,
                           Bsrc + (size_t)(col0 + m) * Cc + kb + scol);
            }
            cp_commit();
            cp_wait<1>();
        } else {
            cp_wait<0>();
        }
        __syncthreads();

        const uint32_t aoff = sA0 + (it & 1) * 128 * GST * 2;
        const uint32_t boff = sB0 + (it & 1) * 128 * GST * 2;
#pragma unroll
        for (int ks = 0; ks < 4; ks++) {
            const int k0 = ks * 16;
            uint32_t a[4][4], b[2][4];
#pragma unroll
            for (int mt = 0; mt < 4; mt++) {
                const uint32_t ad =
                    aoff + ((wm * 64 + mt * 16 + arow) * GST + k0 + acol) * 2;
                LDSM4(a[mt][0], a[mt][1], a[mt][2], a[mt][3], ad);
            }
#pragma unroll
            for (int nt2 = 0; nt2 < 2; nt2++) {
                const uint32_t bd =
                    boff + ((wn * 32 + nt2 * 16 + brow) * GST + k0 + bcol) * 2;
                LDSM4(b[nt2][0], b[nt2][1], b[nt2][2], b[nt2][3], bd);
            }
#pragma unroll
            for (int mt = 0; mt < 4; mt++)
#pragma unroll
                for (int nt2 = 0; nt2 < 2; nt2++) {
                    mma16(c[mt][nt2 * 2 + 0], a[mt], b[nt2][0], b[nt2][1]);
                    mma16(c[mt][nt2 * 2 + 1], a[mt], b[nt2][2], b[nt2][3]);
                }
        }
        __syncthreads();
    }

    // Epilogue
#pragma unroll
    for (int nt = 0; nt < 4; nt++) {
        const int n = col0 + wn * 32 + nt * 8 + tig * 2;
        const float b0 = bias[n], b1 = bias[n + 1];
        if (MODE == 2) {
#pragma unroll
            for (int mt = 0; mt < 4; mt++) {
                const int m = row0 + wm * 64 + mt * 16 + g;
                *(float2*)(Cout + (size_t)m * Cc + n) =
                    make_float2(c[mt][nt][0] + b0, c[mt][nt][1] + b1);
                *(float2*)(Cout + (size_t)(m + 8) * Cc + n) =
                    make_float2(c[mt][nt][2] + b0, c[mt][nt][3] + b1);
            }
        } else {
            const int which = n >> 10;
            const int rem = n & 1023;
            const int h = rem >> 6;
            const int d = rem & 63;
            const int bidx = row0 >> 11;
            const int t0 = row0 & 2047;
            __half* base =
                g_qkv + ((((size_t)which * Bc + bidx) * NH + h) * Tc) * HD + d;
#pragma unroll
            for (int mt = 0; mt < 4; mt++) {
                const int r = t0 + wm * 64 + mt * 16 + g;
                *(__half2*)(base + (size_t)r * HD) =
                    __floats2half2_rn(c[mt][nt][0] + b0, c[mt][nt][1] + b1);
                *(__half2*)(base + (size_t)(r + 8) * HD) =
                    __floats2half2_rn(c[mt][nt][2] + b0, c[mt][nt][3] + b1);
            }
        }
    }
}

// ---------------------------------------------------------------------------
// Flash attention, fp16 mma + ldmatrix. 256 thr (8 warps), q-tile 128,
// warp band 16 q-rows, kv-tiles 64 keys, online softmax fp32.
// Smem stride 72 halves. Per-warp causal tile skip.
// ---------------------------------------------------------------------------
#define FST 72
__global__ void __launch_bounds__(256, 2) flash_mma_kernel() {
    extern __shared__ __half fsm[];
    __half* Qs = fsm;                  // [128][FST]
    __half* Ks = Qs + 128 * FST;       // [64][FST]
    __half* Vs = Ks + 64 * FST;        // [64][FST]
    __half* Ps = Vs + 64 * FST;        // [128][FST]

    const int tid = threadIdx.x;
    const int lane = tid & 31;
    const int w = tid >> 5;
    const int g = lane >> 2;
    const int tig = lane & 3;
    const int band = w * 16;
    const int bh = blockIdx.y;
    const int q0 = blockIdx.x * 128;

    const __half* qb = g_qkv + (size_t)bh * Tc * HD;
    const __half* kb = g_qkv + ((size_t)Bc * NH + bh) * Tc * HD;
    const __half* vb = g_qkv + ((size_t)2 * Bc * NH + bh) * Tc * HD;

    const uint32_t sQ = smem_u32(Qs);
    const uint32_t sK = smem_u32(Ks);
    const uint32_t sV = smem_u32(Vs);
    const uint32_t sP = smem_u32(Ps);

    // stage Q: 128 rows x 64 halves; chunk = 8 halves
    {
        const int r0 = tid >> 3, c8 = (tid & 7) * 8;
#pragma unroll
        for (int l = 0; l < 4; l++) {
            const int r = r0 + 32 * l;
            *(float4*)(Qs + r * FST + c8) =
                *(const float4*)(qb + (size_t)(q0 + r) * HD + c8);
        }
    }
    __syncthreads();

    // ldmatrix lane geometry
    const int arow = (lane & 15);
    const int acol = (lane >> 4) * 8;
    const int brow = (lane & 7) + ((lane >> 4) & 1) * 8;
    const int bcol = ((lane >> 3) & 1) * 8;

    // preload Q fragments (4 k16-steps over HD=64)
    uint32_t qf[4][4];
#pragma unroll
    for (int ks = 0; ks < 4; ks++) {
        const uint32_t ad = sQ + ((band + arow) * FST + ks * 16 + acol) * 2;
        LDSM4(qf[ks][0], qf[ks][1], qf[ks][2], qf[ks][3], ad);
    }

    float o[8][4];
#pragma unroll
    for (int nt = 0; nt < 8; nt++)
#pragma unroll
        for (int j = 0; j < 4; j++) o[nt][j] = 0.0f;
    float m_lo = -1e30f, m_hi = -1e30f, l_lo = 0.0f, l_hi = 0.0f;

    const int row_lo = q0 + band + g;
    const int row_hi = row_lo + 8;
    const int ntiles = 2 * blockIdx.x + 2;

#pragma unroll 1
    for (int kt = 0; kt < ntiles; kt++) {
        const int k0 = kt * 64;
        __syncthreads();
        {
            const int r0 = tid >> 3, c8 = (tid & 7) * 8;
#pragma unroll
            for (int l = 0; l < 2; l++) {
                const int r = r0 + 32 * l;
                *(float4*)(Ks + r * FST + c8) =
                    *(const float4*)(kb + (size_t)(k0 + r) * HD + c8);
                *(float4*)(Vs + r * FST + c8) =
                    *(const float4*)(vb + (size_t)(k0 + r) * HD + c8);
            }
        }
        __syncthreads();

        if (k0 > q0 + band + 15) continue;  // fully masked for this warp

        // S = Q K^T  (64 keys = 4 n16-groups = 8 n-frags)
        float s[8][4];
#pragma unroll
        for (int nt = 0; nt < 8; nt++)
#pragma unroll
            for (int j = 0; j < 4; j++) s[nt][j] = 0.0f;
#pragma unroll
        for (int ks = 0; ks < 4; ks++) {
#pragma unroll
            for (int nt2 = 0; nt2 < 4; nt2++) {
                uint32_t b[4];
                const uint32_t bd =
                    sK + ((nt2 * 16 + brow) * FST + ks * 16 + bcol) * 2;
                LDSM4(b[0], b[1], b[2], b[3], bd);
                mma16(s[nt2 * 2 + 0], qf[ks], b[0], b[1]);
                mma16(s[nt2 * 2 + 1], qf[ks], b[2], b[3]);
            }
        }

        // scale + causal mask
        const bool diag = (k0 + 63 > q0 + band);
#pragma unroll
        for (int nt = 0; nt < 8; nt++) {
            const int cb = k0 + nt * 8 + tig * 2;
            s[nt][0] *= 0.125f; s[nt][1] *= 0.125f;
            s[nt][2] *= 0.125f; s[nt][3] *= 0.125f;
            if (diag) {
                if (cb > row_lo) s[nt][0] = -1e30f;
                if (cb + 1 > row_lo) s[nt][1] = -1e30f;
                if (cb > row_hi) s[nt][2] = -1e30f;
                if (cb + 1 > row_hi) s[nt][3] = -1e30f;
            }
        }

        // row max (quad shuffle over 4 lanes of a row)
        float mx_lo = -1e30f, mx_hi = -1e30f;
#pragma unroll
        for (int nt = 0; nt < 8; nt++) {
            mx_lo = fmaxf(mx_lo, fmaxf(s[nt][0], s[nt][1]));
            mx_hi = fmaxf(mx_hi, fmaxf(s[nt][2], s[nt][3]));
        }
        mx_lo = fmaxf(mx_lo, __shfl_xor_sync(0xffffffffu, mx_lo, 1));
        mx_lo = fmaxf(mx_lo, __shfl_xor_sync(0xffffffffu, mx_lo, 2));
        mx_hi = fmaxf(mx_hi, __shfl_xor_sync(0xffffffffu, mx_hi, 1));
        mx_hi = fmaxf(mx_hi, __shfl_xor_sync(0xffffffffu, mx_hi, 2));

        const float mn_lo = fmaxf(m_lo, mx_lo);
        const float mn_hi = fmaxf(m_hi, mx_hi);
        const float alpha_lo = __expf(m_lo - mn_lo);
        const float alpha_hi = __expf(m_hi - mn_hi);
        m_lo = mn_lo; m_hi = mn_hi;

        float sum_lo = 0.0f, sum_hi = 0.0f;
#pragma unroll
        for (int nt = 0; nt < 8; nt++) {
            s[nt][0] = __expf(s[nt][0] - mn_lo);
            s[nt][1] = __expf(s[nt][1] - mn_lo);
            s[nt][2] = __expf(s[nt][2] - mn_hi);
            s[nt][3] = __expf(s[nt][3] - mn_hi);
            sum_lo += s[nt][0] + s[nt][1];
            sum_hi += s[nt][2] + s[nt][3];
        }
        sum_lo += __shfl_xor_sync(0xffffffffu, sum_lo, 1);
        sum_lo += __shfl_xor_sync(0xffffffffu, sum_lo, 2);
        sum_hi += __shfl_xor_sync(0xffffffffu, sum_hi, 1);
        sum_hi += __shfl_xor_sync(0xffffffffu, sum_hi, 2);
        l_lo = l_lo * alpha_lo + sum_lo;
        l_hi = l_hi * alpha_hi + sum_hi;

        // rescale O; stage P (fp16) into this warp's band
#pragma unroll
        for (int nt = 0; nt < 8; nt++) {
            o[nt][0] *= alpha_lo; o[nt][1] *= alpha_lo;
            o[nt][2] *= alpha_hi; o[nt][3] *= alpha_hi;
            const int cc = nt * 8 + tig * 2;
            *(__half2*)(Ps + (band + g) * FST + cc) =
                __floats2half2_rn(s[nt][0], s[nt][1]);
            *(__half2*)(Ps + (band + g + 8) * FST + cc) =
                __floats2half2_rn(s[nt][2], s[nt][3]);
        }
        __syncwarp();

        // O += P V   (A = P via ldmatrix, B = V^T via ldmatrix.trans)
#pragma unroll
        for (int ks = 0; ks < 4; ks++) {
            uint32_t a[4];
            const uint32_t ad = sP + ((band + arow) * FST + ks * 16 + acol) * 2;
            LDSM4(a[0], a[1], a[2], a[3], ad);
#pragma unroll
            for (int nt2 = 0; nt2 < 4; nt2++) {
                uint32_t b[4];
                const uint32_t bd =
                    sV + ((ks * 16 + arow) * FST + nt2 * 16 + acol) * 2;
                LDSM4T(b[0], b[1], b[2], b[3], bd);
                mma16(o[nt2 * 2 + 0], a, b[0], b[1]);
                mma16(o[nt2 * 2 + 1], a, b[2], b[3]);
            }
        }
    }

    // normalize + store fp16 into g_y [B][T][C]
    const float inv_lo = 1.0f / l_lo;
    const float inv_hi = 1.0f / l_hi;
    const int b = bh / NH;
    const int h = bh % NH;
    const int t_lo = q0 + band + g;
#pragma unroll
    for (int nt = 0; nt < 8; nt++) {
        const int col = h * HD + nt * 8 + tig * 2;
        *(__half2*)(g_y + ((size_t)b * Tc + t_lo) * Cc + col) =
            __floats2half2_rn(o[nt][0] * inv_lo, o[nt][1] * inv_lo);
        *(__half2*)(g_y + ((size_t)b * Tc + t_lo + 8) * Cc + col) =
            __floats2half2_rn(o[nt][2] * inv_hi, o[nt][3] * inv_hi);
    }
}

// ---------------------------------------------------------------------------
extern "C" void kernel_launch(void* const* d_in, const int* in_sizes, int n_in,
                              void* d_out, int out_size) {
    const float* x = (const float*)d_in[0];
    const float* w_attn = (const float*)d_in[1];
    const float* b_attn = (const float*)d_in[2];
    const float* w_proj = (const float*)d_in[3];
    const float* b_proj = (const float*)d_in[4];
    float* out = (float*)d_out;

    // 0) fp16 prep
    cvt_x_kernel<<<(Bc * Tc * Cc) / (256 * 8), 256>>>(x);
    transpose_cvt<0, 3 * Cc><<<dim3(3 * Cc / 32, Cc / 32), dim3(32, 8)>>>(w_attn);
    transpose_cvt<(size_t)3 * Cc * Cc, Cc><<<dim3(Cc / 32, Cc / 32), dim3(32, 8)>>>(w_proj);

    const int gemm_smem = 4 * 128 * GST * 2;  // 73728 B
    cudaFuncSetAttribute(mma_gemm<1>, cudaFuncAttributeMaxDynamicSharedMemorySize, gemm_smem);
    cudaFuncSetAttribute(mma_gemm<2>, cudaFuncAttributeMaxDynamicSharedMemorySize, gemm_smem);

    // 1) QKV = x @ w_attn + b_attn (fp16 mma + cp.async) -> g_qkv
    mma_gemm<1><<<dim3(3 * Cc / 128, Bc * Tc / 128), 256, gemm_smem>>>(b_attn, nullptr);

    // 2) causal flash attention (fp16 mma) -> g_y
    const int fa_smem = (128 + 64 + 64 + 128) * FST * 2;  // 55296 B
    cudaFuncSetAttribute(flash_mma_kernel,
                         cudaFuncAttributeMaxDynamicSharedMemorySize, fa_smem);
    flash_mma_kernel<<<dim3(Tc / 128, Bc * NH), 256, fa_smem>>>();

    // 3) out = y @ w_proj + b_proj (fp16 mma + cp.async)
    mma_gemm<2><<<dim3(Cc / 128, Bc * Tc / 128), 256, gemm_smem>>>(b_proj, out);
}